// round 2
// baseline (speedup 1.0000x reference)
#include <cuda_runtime.h>
#include <cuda_bf16.h>
#include <math.h>

#define B_      32
#define N_      1024
#define C_      512
#define K_      4096
#define NSCALES 11
#define TOT     (B_*N_*C_)      // 16777216
#define MMAX    (B_*1024)       // 32768

// ---------- static device scratch (no allocation allowed) ----------
__device__ float  g_frest[TOT];                       // 64 MB
__device__ float  g_fhat[TOT];                        // 64 MB
__device__ float  g_z[MMAX * C_];                     // 64 MB
__device__ float  g_logits[(size_t)MMAX * K_];        // 512 MB (reused as p)
__device__ float  g_h[MMAX * C_];                     // 64 MB
__device__ float  g_wsq[K_];
__device__ double g_sum;

// TF32 rounding exactly as cuBLAS/tensor-core path (round-to-nearest-away)
__device__ __forceinline__ float tf32r(float x) {
    float y;
    asm("cvt.rna.tf32.f32 %0, %1;" : "=f"(y) : "f"(x));
    return y;
}

// ---------- init: f_rest = f ; f_hat = 0 ; g_sum = 0 ----------
__global__ void init_copy(const float* __restrict__ f) {
    int i = blockIdx.x * blockDim.x + threadIdx.x;   // one float4 each
    ((float4*)g_frest)[i] = ((const float4*)f)[i];
    ((float4*)g_fhat)[i] = make_float4(0.f, 0.f, 0.f, 0.f);
    if (i == 0) g_sum = 0.0;
}

// ---------- w_sq[k] = sum_c W[k,c]^2 ----------
__global__ void wsq_kernel(const float* __restrict__ W) {
    int k = blockIdx.x;
    int tid = threadIdx.x;                           // 128 threads
    float s = 0.f;
#pragma unroll
    for (int i = 0; i < 4; i++) {
        float v = W[k * C_ + tid + i * 128];
        s += v * v;
    }
    for (int o = 16; o; o >>= 1) s += __shfl_xor_sync(0xffffffffu, s, o);
    __shared__ float sr[4];
    if ((tid & 31) == 0) sr[tid >> 5] = s;
    __syncthreads();
    if (tid == 0) g_wsq[k] = sr[0] + sr[1] + sr[2] + sr[3];
}

// ---------- downsample: z[m,c] = mean over block of f_rest ----------
__global__ void downsample_kernel(int pn) {
    int c = blockIdx.y * 128 + threadIdx.x;
    int m = blockIdx.x;
    int b = m / pn;
    int j = m - b * pn;
    int L = N_ / pn;
    const float* src = g_frest + ((size_t)b * N_ + (size_t)j * L) * C_ + c;
    float s0 = 0.f, s1 = 0.f, s2 = 0.f, s3 = 0.f;
    int n = 0;
    for (; n + 4 <= L; n += 4) {
        s0 += src[(n + 0) * C_];
        s1 += src[(n + 1) * C_];
        s2 += src[(n + 2) * C_];
        s3 += src[(n + 3) * C_];
    }
    for (; n < L; n++) s0 += src[n * C_];
    g_z[m * C_ + c] = (s0 + s1 + s2 + s3) * (1.0f / (float)L);
}

// ---------- tiled GEMM emulating TF32 tensor-core numerics ----------
// Operands rounded to TF32 on smem store; fp32 accumulate.
// NT:  C[m,n] = alpha * sum_k A[m*K+k] * B[n*K+k]
// NN:  C[m,n] = alpha * sum_k A[m*K+k] * B[k*N+n]
template <bool NT>
__global__ __launch_bounds__(256)
void gemm128(const float* __restrict__ A, const float* __restrict__ B,
             float* __restrict__ Cm, int M, int N, int K, float alpha)
{
    __shared__ float As[16][128];
    __shared__ float Bs[16][128];
    int tid = threadIdx.x;
    int m0 = blockIdx.y * 128;
    int n0 = blockIdx.x * 128;
    int ty = tid >> 4, tx = tid & 15;

    float acc[8][8];
#pragma unroll
    for (int i = 0; i < 8; i++)
#pragma unroll
        for (int j = 0; j < 8; j++) acc[i][j] = 0.f;

    int a_row = tid >> 2;          // 0..63
    int a_col = (tid & 3) << 2;    // 0,4,8,12
    int bn_row = tid >> 5;         // 0..7
    int bn_col = (tid & 31) << 2;  // 0..124

    for (int kt = 0; kt < K; kt += 16) {
        // A tile (transposed store), TF32-rounded
#pragma unroll
        for (int r = 0; r < 128; r += 64) {
            int gm = m0 + a_row + r;
            float4 v = make_float4(0.f, 0.f, 0.f, 0.f);
            if (gm < M) v = *(const float4*)(A + (size_t)gm * K + kt + a_col);
            As[a_col + 0][a_row + r] = tf32r(v.x);
            As[a_col + 1][a_row + r] = tf32r(v.y);
            As[a_col + 2][a_row + r] = tf32r(v.z);
            As[a_col + 3][a_row + r] = tf32r(v.w);
        }
        // B tile, TF32-rounded
        if (NT) {
#pragma unroll
            for (int r = 0; r < 128; r += 64) {
                int gn = n0 + a_row + r;   // N multiple of 128 here
                float4 v = *(const float4*)(B + (size_t)gn * K + kt + a_col);
                Bs[a_col + 0][a_row + r] = tf32r(v.x);
                Bs[a_col + 1][a_row + r] = tf32r(v.y);
                Bs[a_col + 2][a_row + r] = tf32r(v.z);
                Bs[a_col + 3][a_row + r] = tf32r(v.w);
            }
        } else {
#pragma unroll
            for (int r = 0; r < 16; r += 8) {
                float4 v = *(const float4*)(B + (size_t)(kt + bn_row + r) * N + n0 + bn_col);
                Bs[bn_row + r][bn_col + 0] = tf32r(v.x);
                Bs[bn_row + r][bn_col + 1] = tf32r(v.y);
                Bs[bn_row + r][bn_col + 2] = tf32r(v.z);
                Bs[bn_row + r][bn_col + 3] = tf32r(v.w);
            }
        }
        __syncthreads();
#pragma unroll
        for (int kk = 0; kk < 16; kk++) {
            float a[8], b[8];
            *(float4*)&a[0] = *(const float4*)&As[kk][ty * 8];
            *(float4*)&a[4] = *(const float4*)&As[kk][ty * 8 + 4];
            *(float4*)&b[0] = *(const float4*)&Bs[kk][tx * 8];
            *(float4*)&b[4] = *(const float4*)&Bs[kk][tx * 8 + 4];
#pragma unroll
            for (int i = 0; i < 8; i++)
#pragma unroll
                for (int j = 0; j < 8; j++) acc[i][j] += a[i] * b[j];
        }
        __syncthreads();
    }
#pragma unroll
    for (int i = 0; i < 8; i++) {
        int gm = m0 + ty * 8 + i;
        if (gm < M) {
#pragma unroll
            for (int j = 0; j < 8; j += 4) {
                float4 v = make_float4(acc[i][j] * alpha, acc[i][j + 1] * alpha,
                                       acc[i][j + 2] * alpha, acc[i][j + 3] * alpha);
                *(float4*)(Cm + (size_t)gm * N + n0 + tx * 8 + j) = v;
            }
        }
    }
}

// ---------- softmax over K=4096 (in place), input gets + w_sq[k] ----------
__global__ void softmax_kernel(float* __restrict__ P) {
    int m = blockIdx.x;
    float* row = P + (size_t)m * K_;
    int tid = threadIdx.x;   // 256 threads, 16 elems each
    float x[16];
    float mx = -1e30f;
#pragma unroll
    for (int i = 0; i < 4; i++) {
        int off = tid * 4 + i * 1024;
        float4 v = *(const float4*)(row + off);
        float4 w = *(const float4*)(g_wsq + off);
        x[i * 4 + 0] = v.x + w.x;
        x[i * 4 + 1] = v.y + w.y;
        x[i * 4 + 2] = v.z + w.z;
        x[i * 4 + 3] = v.w + w.w;
    }
#pragma unroll
    for (int i = 0; i < 16; i++) mx = fmaxf(mx, x[i]);
    for (int o = 16; o; o >>= 1) mx = fmaxf(mx, __shfl_xor_sync(0xffffffffu, mx, o));
    __shared__ float smax[8];
    __shared__ float ssum[8];
    if ((tid & 31) == 0) smax[tid >> 5] = mx;
    __syncthreads();
    mx = fmaxf(fmaxf(fmaxf(smax[0], smax[1]), fmaxf(smax[2], smax[3])),
               fmaxf(fmaxf(smax[4], smax[5]), fmaxf(smax[6], smax[7])));
    float s = 0.f;
#pragma unroll
    for (int i = 0; i < 16; i++) { x[i] = expf(__fsub_rn(x[i], mx)); s += x[i]; }
    for (int o = 16; o; o >>= 1) s += __shfl_xor_sync(0xffffffffu, s, o);
    if ((tid & 31) == 0) ssum[tid >> 5] = s;
    __syncthreads();
    s = ssum[0] + ssum[1] + ssum[2] + ssum[3] + ssum[4] + ssum[5] + ssum[6] + ssum[7];
#pragma unroll
    for (int i = 0; i < 4; i++) {
        int off = tid * 4 + i * 1024;
        float4 v = make_float4(__fdiv_rn(x[i * 4 + 0], s), __fdiv_rn(x[i * 4 + 1], s),
                               __fdiv_rn(x[i * 4 + 2], s), __fdiv_rn(x[i * 4 + 3], s));
        *(float4*)(row + off) = v;
    }
}

// ---------- upsample + f_hat/f_rest update + sum((f_hat-f)^2) (+ final out) ----------
__global__ void update_kernel(const float* __restrict__ f, float* __restrict__ out,
                              int pn, int last)
{
    int i4 = blockIdx.x * blockDim.x + threadIdx.x;
    int idx = i4 << 2;
    int c = idx & (C_ - 1);
    int n = (idx >> 9) & (N_ - 1);
    int b = idx >> 19;

    float scale = (float)pn / (float)N_;
    float coord = __fsub_rn(__fmul_rn((float)n + 0.5f, scale), 0.5f);
    coord = fminf(fmaxf(coord, 0.0f), (float)(pn - 1));
    int i0 = (int)floorf(coord);
    int i1 = min(i0 + 1, pn - 1);
    float w = __fsub_rn(coord, (float)i0);
    float om = __fsub_rn(1.0f, w);

    const float* h0 = g_h + (size_t)(b * pn + i0) * C_ + c;
    const float* h1 = g_h + (size_t)(b * pn + i1) * C_ + c;
    float4 ha = *(const float4*)h0;
    float4 hb = *(const float4*)h1;
    float4 fh = *(const float4*)(g_fhat + idx);
    float4 fr = *(const float4*)(g_frest + idx);
    float4 fv = *(const float4*)(f + idx);

    // up = h0*(1-w) + h1*w, each step RNE, no contraction (match jax)
    float up0 = __fadd_rn(__fmul_rn(ha.x, om), __fmul_rn(hb.x, w));
    float up1 = __fadd_rn(__fmul_rn(ha.y, om), __fmul_rn(hb.y, w));
    float up2 = __fadd_rn(__fmul_rn(ha.z, om), __fmul_rn(hb.z, w));
    float up3 = __fadd_rn(__fmul_rn(ha.w, om), __fmul_rn(hb.w, w));

    fh.x = __fadd_rn(fh.x, up0); fh.y = __fadd_rn(fh.y, up1);
    fh.z = __fadd_rn(fh.z, up2); fh.w = __fadd_rn(fh.w, up3);
    fr.x = __fsub_rn(fr.x, up0); fr.y = __fsub_rn(fr.y, up1);
    fr.z = __fsub_rn(fr.z, up2); fr.w = __fsub_rn(fr.w, up3);
    *(float4*)(g_fhat + idx) = fh;
    *(float4*)(g_frest + idx) = fr;

    // t = f_hat - f (exactly the rounding the reference performs)
    float t0 = __fsub_rn(fh.x, fv.x);
    float t1 = __fsub_rn(fh.y, fv.y);
    float t2 = __fsub_rn(fh.z, fv.z);
    float t3 = __fsub_rn(fh.w, fv.w);

    float sq = t0 * t0 + t1 * t1 + t2 * t2 + t3 * t3;

    if (last) {
        // straight-through: (f_hat - f) + f, both roundings kept
        float4 o = make_float4(__fadd_rn(t0, fv.x), __fadd_rn(t1, fv.y),
                               __fadd_rn(t2, fv.z), __fadd_rn(t3, fv.w));
        *(float4*)(out + idx) = o;
    }

    for (int o = 16; o; o >>= 1) sq += __shfl_xor_sync(0xffffffffu, sq, o);
    __shared__ float sred[8];
    int tid = threadIdx.x;
    if ((tid & 31) == 0) sred[tid >> 5] = sq;
    __syncthreads();
    if (tid == 0) {
        float t = sred[0] + sred[1] + sred[2] + sred[3] +
                  sred[4] + sred[5] + sred[6] + sred[7];
        atomicAdd(&g_sum, (double)t);
    }
}

// ---------- scalars ----------
__global__ void finalize_kernel(float* __restrict__ out) {
    double mean = g_sum / ((double)TOT * (double)NSCALES);
    out[TOT]     = (float)(0.25 * mean);   // commit
    out[TOT + 1] = (float)mean;            // qlat
}

extern "C" void kernel_launch(void* const* d_in, const int* in_sizes, int n_in,
                              void* d_out, int out_size)
{
    const float* f = (const float*)d_in[0];   // (B, N, C) fp32
    const float* W = (const float*)d_in[1];   // (K, C)    fp32
    float* out = (float*)d_out;

    float *zp = nullptr, *lp = nullptr, *hp = nullptr;
    cudaGetSymbolAddress((void**)&zp, g_z);
    cudaGetSymbolAddress((void**)&lp, g_logits);
    cudaGetSymbolAddress((void**)&hp, g_h);

    init_copy<<<TOT / 4 / 256, 256>>>(f);
    wsq_kernel<<<K_, 128>>>(W);

    for (int s = 0; s < NSCALES; s++) {
        int pn = 1 << s;
        int M = B_ * pn;
        downsample_kernel<<<dim3(M, C_ / 128), 128>>>(pn);
        // logits = -2 * z @ W^T   (M x 4096, contraction over C=512), TF32 numerics
        gemm128<true><<<dim3(K_ / 128, (M + 127) / 128), 256>>>(
            zp, W, lp, M, K_, C_, -2.0f);
        softmax_kernel<<<M, 256>>>(lp);
        // h = p @ W   (M x 512, contraction over K=4096), TF32 numerics
        gemm128<false><<<dim3(C_ / 128, (M + 127) / 128), 256>>>(
            lp, W, hp, M, C_, K_, 1.0f);
        update_kernel<<<TOT / 4 / 256, 256>>>(f, out, pn, s == NSCALES - 1 ? 1 : 0);
    }
    finalize_kernel<<<1, 1>>>(out);
}

// round 4
// speedup vs baseline: 3.5953x; 3.5953x over previous
#include <cuda_runtime.h>
#include <cuda_bf16.h>
#include <math.h>
#include <stdint.h>

#define B_      32
#define N_      1024
#define C_      512
#define K_      4096
#define NSCALES 11
#define TOT     (B_*N_*C_)      // 16777216
#define MMAX    (B_*1024)       // 32768

// ---------- static device scratch ----------
__device__ float  g_frest[TOT];
__device__ float  g_fhat[TOT];
__device__ float  g_z[MMAX * C_];
__device__ float  g_logits[(size_t)MMAX * K_];
__device__ float  g_h[MMAX * C_];
__device__ float  g_wr[K_ * C_];     // tf32-rounded W   (4096 x 512)
__device__ float  g_wt[C_ * K_];     // tf32-rounded W^T (512 x 4096)
__device__ float  g_wsq[K_];
__device__ double g_sum;

// ---------- helpers ----------
__device__ __forceinline__ float tf32r(float x) {
    float y;
    asm("cvt.rna.tf32.f32 %0, %1;" : "=f"(y) : "f"(x));
    return y;
}
__device__ __forceinline__ uint32_t smem_u32(const void* p) {
    uint32_t a;
    asm("{ .reg .u64 t; cvta.to.shared.u64 t, %1; cvt.u32.u64 %0, t; }" : "=r"(a) : "l"(p));
    return a;
}
__device__ __forceinline__ void cp_async16(uint32_t saddr, const void* gaddr) {
    asm volatile("cp.async.cg.shared.global [%0], [%1], 16;" :: "r"(saddr), "l"(gaddr));
}
__device__ __forceinline__ void cp_commit() {
    asm volatile("cp.async.commit_group;" ::: "memory");
}
__device__ __forceinline__ void ldm_x4(uint32_t* r, uint32_t addr) {
    asm volatile("ldmatrix.sync.aligned.m8n8.x4.shared.b16 {%0,%1,%2,%3}, [%4];"
                 : "=r"(r[0]), "=r"(r[1]), "=r"(r[2]), "=r"(r[3]) : "r"(addr));
}
__device__ __forceinline__ void mma_tf32(float* d, const uint32_t* a, const uint32_t* b) {
    asm volatile(
        "mma.sync.aligned.m16n8k8.row.col.f32.tf32.tf32.f32 "
        "{%0,%1,%2,%3}, {%4,%5,%6,%7}, {%8,%9}, {%0,%1,%2,%3};"
        : "+f"(d[0]), "+f"(d[1]), "+f"(d[2]), "+f"(d[3])
        : "r"(a[0]), "r"(a[1]), "r"(a[2]), "r"(a[3]), "r"(b[0]), "r"(b[1]));
}

// ---------- init ----------
__global__ void init_copy(const float* __restrict__ f) {
    int i = blockIdx.x * blockDim.x + threadIdx.x;
    ((float4*)g_frest)[i] = ((const float4*)f)[i];
    ((float4*)g_fhat)[i] = make_float4(0.f, 0.f, 0.f, 0.f);
    if (i == 0) g_sum = 0.0;
}

// ---------- prep: w_sq (raw W) + tf32-rounded W and W^T ----------
__global__ void prep_w(const float* __restrict__ W) {
    int k = blockIdx.x;
    int tid = threadIdx.x;                           // 128 threads
    float s = 0.f;
#pragma unroll
    for (int i = 0; i < 4; i++) {
        int c = tid + i * 128;
        float v = W[k * C_ + c];
        s += v * v;
        float r = tf32r(v);
        g_wr[k * C_ + c] = r;
        g_wt[(size_t)c * K_ + k] = r;
    }
    for (int o = 16; o; o >>= 1) s += __shfl_xor_sync(0xffffffffu, s, o);
    __shared__ float sr[4];
    if ((tid & 31) == 0) sr[tid >> 5] = s;
    __syncthreads();
    if (tid == 0) g_wsq[k] = sr[0] + sr[1] + sr[2] + sr[3];
}

// ---------- downsample (tf32-rounded output) ----------
__global__ void downsample_kernel(int pn) {
    int c = blockIdx.y * 128 + threadIdx.x;
    int m = blockIdx.x;
    int b = m / pn;
    int j = m - b * pn;
    int L = N_ / pn;
    const float* src = g_frest + ((size_t)b * N_ + (size_t)j * L) * C_ + c;
    float s0 = 0.f, s1 = 0.f, s2 = 0.f, s3 = 0.f;
    int n = 0;
    for (; n + 4 <= L; n += 4) {
        s0 += src[(n + 0) * C_];
        s1 += src[(n + 1) * C_];
        s2 += src[(n + 2) * C_];
        s3 += src[(n + 3) * C_];
    }
    for (; n < L; n++) s0 += src[n * C_];
    g_z[m * C_ + c] = tf32r((s0 + s1 + s2 + s3) * (1.0f / (float)L));
}

// ---------- mma.sync tf32 GEMM (NT): D[m,n] = alpha * sum_k A[m,k]*B[n,k] ----------
// Tile 128x128, BK=32, 256 threads (8 warps: 2 in M x 4 in N; warp tile 64x32).
// A/B staged in smem with XOR(16B-unit) swizzle; fragments via ldmatrix.b16 (tf32-as-b32).
#define TILE_M 128
#define TILE_N 128
#define BK     32
#define STAGE_FLOATS ((TILE_M + TILE_N) * BK)      // 8192 floats = 32 KB
#define GEMM_SMEM    (2 * STAGE_FLOATS * 4)        // 64 KB

__global__ __launch_bounds__(256, 1)
void gemm_mma(const float* __restrict__ A, const float* __restrict__ B,
              float* __restrict__ D, int M, int lda, int ldb, int Ntot, int Ktot,
              float alpha)
{
    extern __shared__ float smem[];
    int tid = threadIdx.x, wid = tid >> 5, lane = tid & 31;
    int m0 = blockIdx.y * TILE_M, n0 = blockIdx.x * TILE_N;
    int wm = wid & 1, wn = wid >> 1;           // warp coords
    uint32_t sbase = smem_u32(smem);

    float acc[4][4][4];
#pragma unroll
    for (int i = 0; i < 4; i++)
#pragma unroll
        for (int j = 0; j < 4; j++)
#pragma unroll
            for (int q = 0; q < 4; q++) acc[i][j][q] = 0.f;

    // global->smem mapping: 8 float4 per thread per stage (4 for A, 4 for B)
    // idx = i*256+tid -> r = idx>>3 (0..127), u = idx&7 (16B unit)
    int ld_r = tid >> 3;
    int ld_u = tid & 7;

    // ldmatrix per-thread invariants
    int arow = wm * 64 + (lane & 15);          // + mf*16
    int ahk  = (lane >> 4) & 1;
    int brow = wn * 32 + (lane & 7) + ((lane & 16) ? 8 : 0);  // + g*16
    int sw   = lane & 7;                        // row&7 for both (offsets mult of 8)

    int NS = Ktot / BK;

    // ---- prologue: stage 0 ----
    {
        const float* Ag = A + (size_t)min(m0 + ld_r, M - 1) * lda;
        const float* Bg = B + (size_t)(n0 + ld_r) * ldb;
#pragma unroll
        for (int i = 0; i < 4; i++) {
            int r = ld_r + i * 32;
            int rr = min(m0 + r, M - 1);
            uint32_t sa = sbase + ((r * 8 + (ld_u ^ (r & 7))) << 4);
            cp_async16(sa, A + (size_t)rr * lda + ld_u * 4);
            uint32_t sb2 = sbase + ((TILE_M * BK) << 2) + ((r * 8 + (ld_u ^ (r & 7))) << 4);
            cp_async16(sb2, B + (size_t)(n0 + r) * ldb + ld_u * 4);
        }
        cp_commit();
        (void)Ag; (void)Bg;
    }

    for (int s = 0; s < NS; s++) {
        int cur = s & 1;
        uint32_t curbase = sbase + cur * (STAGE_FLOATS << 2);
        // prefetch next stage
        if (s + 1 < NS) {
            int nxt = (s + 1) & 1;
            uint32_t nbase = sbase + nxt * (STAGE_FLOATS << 2);
            int kt = (s + 1) * BK;
#pragma unroll
            for (int i = 0; i < 4; i++) {
                int r = ld_r + i * 32;
                int rr = min(m0 + r, M - 1);
                uint32_t sa = nbase + ((r * 8 + (ld_u ^ (r & 7))) << 4);
                cp_async16(sa, A + (size_t)rr * lda + kt + ld_u * 4);
                uint32_t sb2 = nbase + ((TILE_M * BK) << 2) + ((r * 8 + (ld_u ^ (r & 7))) << 4);
                cp_async16(sb2, B + (size_t)(n0 + r) * ldb + kt + ld_u * 4);
            }
            cp_commit();
            asm volatile("cp.async.wait_group 1;" ::: "memory");
        } else {
            asm volatile("cp.async.wait_group 0;" ::: "memory");
        }
        __syncthreads();

        uint32_t sA = curbase;
        uint32_t sB = curbase + ((TILE_M * BK) << 2);
#pragma unroll
        for (int ks = 0; ks < 4; ks++) {
            uint32_t bfr[4][2];
#pragma unroll
            for (int g = 0; g < 2; g++) {
                uint32_t r4[4];
                int row = brow + g * 16;
                int bhk = (lane >> 3) & 1;
                uint32_t addr = sB + ((row * 8 + ((ks * 2 + bhk) ^ sw)) << 4);
                ldm_x4(r4, addr);
                bfr[2 * g + 0][0] = r4[0]; bfr[2 * g + 0][1] = r4[1];
                bfr[2 * g + 1][0] = r4[2]; bfr[2 * g + 1][1] = r4[3];
            }
#pragma unroll
            for (int mf = 0; mf < 4; mf++) {
                uint32_t afr[4];
                int row = arow + mf * 16;
                uint32_t addr = sA + ((row * 8 + ((ks * 2 + ahk) ^ sw)) << 4);
                ldm_x4(afr, addr);
#pragma unroll
                for (int nf = 0; nf < 4; nf++)
                    mma_tf32(acc[mf][nf], afr, bfr[nf]);
            }
        }
        __syncthreads();
    }

    // ---- epilogue ----
    int er = lane >> 2;            // 0..7
    int ec = (lane & 3) * 2;
#pragma unroll
    for (int mf = 0; mf < 4; mf++) {
#pragma unroll
        for (int half = 0; half < 2; half++) {
            int row = m0 + wm * 64 + mf * 16 + er + half * 8;
            if (row < M) {
                float* Drow = D + (size_t)row * Ntot + n0 + wn * 32 + ec;
#pragma unroll
                for (int nf = 0; nf < 4; nf++) {
                    float2 v;
                    v.x = acc[mf][nf][half * 2 + 0] * alpha;
                    v.y = acc[mf][nf][half * 2 + 1] * alpha;
                    *(float2*)(Drow + nf * 8) = v;
                }
            }
        }
    }
}

// ---------- softmax over K=4096 (in place), + w_sq, output tf32-rounded ----------
__global__ void softmax_kernel(float* __restrict__ P) {
    int m = blockIdx.x;
    float* row = P + (size_t)m * K_;
    int tid = threadIdx.x;   // 256 threads, 16 elems each
    float x[16];
    float mx = -1e30f;
#pragma unroll
    for (int i = 0; i < 4; i++) {
        int off = tid * 4 + i * 1024;
        float4 v = *(const float4*)(row + off);
        float4 w = *(const float4*)(g_wsq + off);
        x[i * 4 + 0] = v.x + w.x;
        x[i * 4 + 1] = v.y + w.y;
        x[i * 4 + 2] = v.z + w.z;
        x[i * 4 + 3] = v.w + w.w;
    }
#pragma unroll
    for (int i = 0; i < 16; i++) mx = fmaxf(mx, x[i]);
    for (int o = 16; o; o >>= 1) mx = fmaxf(mx, __shfl_xor_sync(0xffffffffu, mx, o));
    __shared__ float smax[8];
    __shared__ float ssum[8];
    if ((tid & 31) == 0) smax[tid >> 5] = mx;
    __syncthreads();
    mx = fmaxf(fmaxf(fmaxf(smax[0], smax[1]), fmaxf(smax[2], smax[3])),
               fmaxf(fmaxf(smax[4], smax[5]), fmaxf(smax[6], smax[7])));
    float s = 0.f;
#pragma unroll
    for (int i = 0; i < 16; i++) { x[i] = expf(__fsub_rn(x[i], mx)); s += x[i]; }
    for (int o = 16; o; o >>= 1) s += __shfl_xor_sync(0xffffffffu, s, o);
    if ((tid & 31) == 0) ssum[tid >> 5] = s;
    __syncthreads();
    s = ssum[0] + ssum[1] + ssum[2] + ssum[3] + ssum[4] + ssum[5] + ssum[6] + ssum[7];
#pragma unroll
    for (int i = 0; i < 4; i++) {
        int off = tid * 4 + i * 1024;
        float4 v = make_float4(tf32r(__fdiv_rn(x[i * 4 + 0], s)),
                               tf32r(__fdiv_rn(x[i * 4 + 1], s)),
                               tf32r(__fdiv_rn(x[i * 4 + 2], s)),
                               tf32r(__fdiv_rn(x[i * 4 + 3], s)));
        *(float4*)(row + off) = v;
    }
}

// ---------- upsample + f_hat/f_rest update + loss accum (+ final out) ----------
__global__ void update_kernel(const float* __restrict__ f, float* __restrict__ out,
                              int pn, int last)
{
    int i4 = blockIdx.x * blockDim.x + threadIdx.x;
    int idx = i4 << 2;
    int c = idx & (C_ - 1);
    int n = (idx >> 9) & (N_ - 1);
    int b = idx >> 19;

    float scale = (float)pn / (float)N_;
    float coord = __fsub_rn(__fmul_rn((float)n + 0.5f, scale), 0.5f);
    coord = fminf(fmaxf(coord, 0.0f), (float)(pn - 1));
    int i0 = (int)floorf(coord);
    int i1 = min(i0 + 1, pn - 1);
    float w = __fsub_rn(coord, (float)i0);
    float om = __fsub_rn(1.0f, w);

    const float* h0 = g_h + (size_t)(b * pn + i0) * C_ + c;
    const float* h1 = g_h + (size_t)(b * pn + i1) * C_ + c;
    float4 ha = *(const float4*)h0;
    float4 hb = *(const float4*)h1;
    float4 fh = *(const float4*)(g_fhat + idx);
    float4 fr = *(const float4*)(g_frest + idx);
    float4 fv = *(const float4*)(f + idx);

    float up0 = __fadd_rn(__fmul_rn(ha.x, om), __fmul_rn(hb.x, w));
    float up1 = __fadd_rn(__fmul_rn(ha.y, om), __fmul_rn(hb.y, w));
    float up2 = __fadd_rn(__fmul_rn(ha.z, om), __fmul_rn(hb.z, w));
    float up3 = __fadd_rn(__fmul_rn(ha.w, om), __fmul_rn(hb.w, w));

    fh.x = __fadd_rn(fh.x, up0); fh.y = __fadd_rn(fh.y, up1);
    fh.z = __fadd_rn(fh.z, up2); fh.w = __fadd_rn(fh.w, up3);
    fr.x = __fsub_rn(fr.x, up0); fr.y = __fsub_rn(fr.y, up1);
    fr.z = __fsub_rn(fr.z, up2); fr.w = __fsub_rn(fr.w, up3);
    *(float4*)(g_fhat + idx) = fh;
    *(float4*)(g_frest + idx) = fr;

    float t0 = __fsub_rn(fh.x, fv.x);
    float t1 = __fsub_rn(fh.y, fv.y);
    float t2 = __fsub_rn(fh.z, fv.z);
    float t3 = __fsub_rn(fh.w, fv.w);

    float sq = t0 * t0 + t1 * t1 + t2 * t2 + t3 * t3;

    if (last) {
        float4 o = make_float4(__fadd_rn(t0, fv.x), __fadd_rn(t1, fv.y),
                               __fadd_rn(t2, fv.z), __fadd_rn(t3, fv.w));
        *(float4*)(out + idx) = o;
    }

    for (int o = 16; o; o >>= 1) sq += __shfl_xor_sync(0xffffffffu, sq, o);
    __shared__ float sred[8];
    int tid = threadIdx.x;
    if ((tid & 31) == 0) sred[tid >> 5] = sq;
    __syncthreads();
    if (tid == 0) {
        float t = sred[0] + sred[1] + sred[2] + sred[3] +
                  sred[4] + sred[5] + sred[6] + sred[7];
        atomicAdd(&g_sum, (double)t);
    }
}

// ---------- scalars ----------
__global__ void finalize_kernel(float* __restrict__ out) {
    double mean = g_sum / ((double)TOT * (double)NSCALES);
    out[TOT]     = (float)(0.25 * mean);   // commit
    out[TOT + 1] = (float)mean;            // qlat
}

extern "C" void kernel_launch(void* const* d_in, const int* in_sizes, int n_in,
                              void* d_out, int out_size)
{
    const float* f = (const float*)d_in[0];   // (B, N, C) fp32
    const float* W = (const float*)d_in[1];   // (K, C)    fp32
    float* out = (float*)d_out;

    float *zp = nullptr, *lp = nullptr, *hp = nullptr, *wr = nullptr, *wt = nullptr;
    cudaGetSymbolAddress((void**)&zp, g_z);
    cudaGetSymbolAddress((void**)&lp, g_logits);
    cudaGetSymbolAddress((void**)&hp, g_h);
    cudaGetSymbolAddress((void**)&wr, g_wr);
    cudaGetSymbolAddress((void**)&wt, g_wt);

    cudaFuncSetAttribute(gemm_mma, cudaFuncAttributeMaxDynamicSharedMemorySize, GEMM_SMEM);

    init_copy<<<TOT / 4 / 256, 256>>>(f);
    prep_w<<<K_, 128>>>(W);

    for (int s = 0; s < NSCALES; s++) {
        int pn = 1 << s;
        int M = B_ * pn;
        int mt = (M + TILE_M - 1) / TILE_M;
        downsample_kernel<<<dim3(M, C_ / 128), 128>>>(pn);
        // logits = -2 * z @ Wr^T : A=z (lda=512), B=Wr (ldb=512), Ntot=4096, K=512
        gemm_mma<<<dim3(K_ / TILE_N, mt), 256, GEMM_SMEM>>>(
            zp, wr, lp, M, C_, C_, K_, C_, -2.0f);
        softmax_kernel<<<M, 256>>>(lp);
        // h = p @ W : NT with B = Wt (512 x 4096), Ntot=512, K=4096
        gemm_mma<<<dim3(C_ / TILE_N, mt), 256, GEMM_SMEM>>>(
            lp, wt, hp, M, K_, K_, C_, K_, 1.0f);
        update_kernel<<<TOT / 4 / 256, 256>>>(f, out, pn, s == NSCALES - 1 ? 1 : 0);
    }
    finalize_kernel<<<1, 1>>>(out);
}